// round 2
// baseline (speedup 1.0000x reference)
#include <cuda_runtime.h>
#include <math.h>

#define S 1024
#define SS (S*S)
#define NTILE 32            // tiles per dim (32x32 pixels each)
#define NTILES (NTILE*NTILE)
#define MAXR 256
#define NKP 17
#define NEG_INF (-INFINITY)

__device__ float g_scores[SS];
__device__ float g_tileMax[NTILES];
__device__ int   g_tileIdx[NTILES];
__device__ int   g_rootX[MAXR];
__device__ int   g_rootY[MAXR];
__device__ int   g_valid[MAXR];

// ---- XLA-compatible fast tanh (Eigen rational, FMA path) ----
__device__ __forceinline__ float xla_tanh(float x) {
    const float kClamp = 7.99881172180175781f;
    float xc = fminf(fmaxf(x, -kClamp), kClamp);
    float x2 = xc * xc;
    float num = -2.76076847742355e-16f;
    num = fmaf(num, x2, 2.00018790482477e-13f);
    num = fmaf(num, x2, -8.60467152213735e-11f);
    num = fmaf(num, x2, 5.12229709037114e-08f);
    num = fmaf(num, x2, 1.48572235717979e-05f);
    num = fmaf(num, x2, 6.37261928875436e-04f);
    num = fmaf(num, x2, 4.89352455891786e-03f);
    num = num * xc;
    float den = 1.19825839466702e-06f;
    den = fmaf(den, x2, 1.18534705686654e-04f);
    den = fmaf(den, x2, 2.26843463243900e-03f);
    den = fmaf(den, x2, 4.89352518554385e-03f);
    float r = num / den;
    return (fabsf(x) < 0.0004f) ? x : r;
}

// XLA logistic = 0.5 + 0.5*tanh(0.5*x)   (0.5 scalings are exact in fp32)
__device__ __forceinline__ float xla_logistic(float x) {
    return 0.5f + 0.5f * xla_tanh(0.5f * x);
}

// argmax combine: higher value wins; tie -> lower linear index (jnp.argmax first-occurrence)
__device__ __forceinline__ void amax(float& v, int& i, float ov, int oi) {
    if (ov > v || (ov == v && oi < i)) { v = ov; i = oi; }
}

// ---- Kernel A: score map + per-tile argmax ----
__global__ void kA_scores(const float* __restrict__ in) {
    __shared__ float wV[32];
    __shared__ int   wI[32];
    int tx = threadIdx.x, ty = threadIdx.y;
    int x = blockIdx.x * 32 + tx;
    int y = blockIdx.y * 32 + ty;
    int idx = (y << 10) + x;
    float v = in[idx];                 // channel 0
    float conf = xla_logistic(v);
    float s = (conf > 0.8f) ? conf : NEG_INF;
    g_scores[idx] = s;

    float mv = s; int mi = idx;
    #pragma unroll
    for (int off = 16; off; off >>= 1) {
        float ov = __shfl_down_sync(0xFFFFFFFFu, mv, off);
        int   oi = __shfl_down_sync(0xFFFFFFFFu, mi, off);
        amax(mv, mi, ov, oi);
    }
    if (tx == 0) { wV[ty] = mv; wI[ty] = mi; }
    __syncthreads();
    if (ty == 0) {
        mv = wV[tx]; mi = wI[tx];
        #pragma unroll
        for (int off = 16; off; off >>= 1) {
            float ov = __shfl_down_sync(0xFFFFFFFFu, mv, off);
            int   oi = __shfl_down_sync(0xFFFFFFFFu, mi, off);
            amax(mv, mi, ov, oi);
        }
        if (tx == 0) {
            int t = blockIdx.y * NTILE + blockIdx.x;
            g_tileMax[t] = mv;
            g_tileIdx[t] = mi;
        }
    }
}

// ---- Kernel B: sequential greedy NMS (single block) ----
__global__ void __launch_bounds__(1024, 1) kB_nms() {
    __shared__ float sVal[NTILES];
    __shared__ int   sIdx[NTILES];
    __shared__ float wV[32];
    __shared__ int   wI[32];
    __shared__ float tV[32];
    __shared__ int   tI[32];
    __shared__ float sBestV;
    __shared__ int   sBestI;

    int tid  = threadIdx.x;
    int lane = tid & 31;
    int warp = tid >> 5;

    sVal[tid] = g_tileMax[tid];
    sIdx[tid] = g_tileIdx[tid];
    __syncthreads();

    for (int r = 0; r < MAXR; r++) {
        // ---- global argmax over 1024 tile maxima ----
        float mv = sVal[tid]; int mi = sIdx[tid];
        #pragma unroll
        for (int off = 16; off; off >>= 1) {
            float ov = __shfl_down_sync(0xFFFFFFFFu, mv, off);
            int   oi = __shfl_down_sync(0xFFFFFFFFu, mi, off);
            amax(mv, mi, ov, oi);
        }
        if (lane == 0) { wV[warp] = mv; wI[warp] = mi; }
        __syncthreads();
        if (warp == 0) {
            mv = wV[lane]; mi = wI[lane];
            #pragma unroll
            for (int off = 16; off; off >>= 1) {
                float ov = __shfl_down_sync(0xFFFFFFFFu, mv, off);
                int   oi = __shfl_down_sync(0xFFFFFFFFu, mi, off);
                amax(mv, mi, ov, oi);
            }
            if (lane == 0) {
                sBestV = mv; sBestI = mi;
                g_rootX[r] = mi & (S - 1);
                g_rootY[r] = mi >> 10;
                g_valid[r] = (mv > NEG_INF) ? 1 : 0;   // isfinite(best)
            }
        }
        __syncthreads();

        int bI = sBestI;
        int cx = bI & (S - 1);
        int cy = bI >> 10;

        // affected tiles: those intersecting the 21x21 suppression box
        int tx0 = max(cx - 10, 0) >> 5, tx1 = min(cx + 10, S - 1) >> 5;
        int ty0 = max(cy - 10, 0) >> 5, ty1 = min(cy + 10, S - 1) >> 5;
        int ntx = tx1 - tx0 + 1;
        int nty = ty1 - ty0 + 1;
        int nt  = ntx * nty;            // <= 4

        int ti = tid >> 8;              // tile slot 0..3 (256 threads/tile)
        int p  = tid & 255;

        float mv2 = NEG_INF; int mi2 = 0x7FFFFFFF;
        if (ti < nt) {
            int ttx = tx0 + (ti % ntx);
            int tty = ty0 + (ti / ntx);
            int tbx = ttx << 5, tby = tty << 5;
            #pragma unroll
            for (int q = 0; q < 4; q++) {
                int pp = p + q * 256;               // 0..1023, row-major in tile
                int py = tby + (pp >> 5);
                int px = tbx + (pp & 31);
                int pix = (py << 10) + px;
                float s = g_scores[pix];
                int dx = px - cx, dy = py - cy;
                if (dx * dx + dy * dy <= 100) {     // DIST_THR^2, exact int
                    g_scores[pix] = NEG_INF;
                    s = NEG_INF;
                }
                amax(mv2, mi2, s, pix);
            }
        }
        // warp reduce (each warp lies fully inside one tile slot)
        #pragma unroll
        for (int off = 16; off; off >>= 1) {
            float ov = __shfl_down_sync(0xFFFFFFFFu, mv2, off);
            int   oi = __shfl_down_sync(0xFFFFFFFFu, mi2, off);
            amax(mv2, mi2, ov, oi);
        }
        if (lane == 0) { tV[warp] = mv2; tI[warp] = mi2; }
        __syncthreads();
        if (tid < nt) {
            float bv = NEG_INF; int bi = 0x7FFFFFFF;
            #pragma unroll
            for (int w = 0; w < 8; w++) amax(bv, bi, tV[tid * 8 + w], tI[tid * 8 + w]);
            int ttx = tx0 + (tid % ntx);
            int tty = ty0 + (tid / ntx);
            int tt  = tty * NTILE + ttx;
            sVal[tt] = bv;
            sIdx[tt] = bi;
        }
        __syncthreads();
    }
}

// ---- Kernel C: displacement gather + outputs ----
// out layout (float32, 9472 elems): root[256][2] | kp[256][17][2] | valid[256]
__global__ void kC_gather(const float* __restrict__ in, float* __restrict__ out) {
    int r = blockIdx.x;
    int k = threadIdx.x;
    int cx = g_rootX[r];
    int cy = g_rootY[r];
    float m = g_valid[r] ? 1.0f : 0.0f;
    float z = sqrtf(2.0f) * 1024.0f;

    if (k < NKP) {
        int base = (1 + 2 * k) * SS + (cy << 10) + cx;
        float dx = xla_tanh(in[base]);
        float dy = xla_tanh(in[base + SS]);
        float kx = dx * z + (float)cx;
        float ky = dy * z + (float)cy;
        float ddx = kx - (float)cx;
        float ddy = ky - (float)cy;
        float d = sqrtf(ddx * ddx + ddy * ddy);
        if (d < 2.0f) { kx = 0.0f; ky = 0.0f; }
        out[512 + r * 34 + 2 * k]     = kx * m * 4.0f;
        out[512 + r * 34 + 2 * k + 1] = ky * m * 4.0f;
    }
    if (k == NKP) {
        out[r * 2]     = (float)cx * m * 4.0f;
        out[r * 2 + 1] = (float)cy * m * 4.0f;
        out[512 + 256 * 34 + r] = m;
    }
}

extern "C" void kernel_launch(void* const* d_in, const int* in_sizes, int n_in,
                              void* d_out, int out_size) {
    const float* x = (const float*)d_in[0];
    float* out = (float*)d_out;

    dim3 blkA(32, 32), grdA(32, 32);
    kA_scores<<<grdA, blkA>>>(x);
    kB_nms<<<1, 1024>>>();
    kC_gather<<<MAXR, 32>>>(x, out);
}

// round 4
// speedup vs baseline: 5.2215x; 5.2215x over previous
#include <cuda_runtime.h>
#include <math.h>

#define S 1024
#define SS (S*S)
#define NTILE 32
#define NTILES (NTILE*NTILE)
#define MAXR 256
#define NKP 17
#define NEG_INF (-INFINITY)

#define NB 3281              // histogram bins over score bits [0x3F4CC000, 0x3F800000]
#define B0BITS 0x3F4CC000u
#define CAP 2048             // max selected candidates (sorted)
#define KTGT 1536            // selection target (expected need ~270)

__device__ float g_scores[SS];
__device__ float g_tileMax[NTILES];
__device__ int   g_tileIdx[NTILES];
__device__ int   g_rootX[MAXR];
__device__ int   g_rootY[MAXR];
__device__ int   g_valid[MAXR];
__device__ int   g_hist[NB];
__device__ unsigned long long g_sel[CAP];
__device__ int   g_selCount;
__device__ unsigned g_thrBits;
__device__ int   g_totalCand;
__device__ int   g_fallback;

// ---- XLA-compatible fast tanh (Eigen rational, FMA path) ----
__device__ __forceinline__ float xla_tanh(float x) {
    const float kClamp = 7.99881172180175781f;
    float xc = fminf(fmaxf(x, -kClamp), kClamp);
    float x2 = xc * xc;
    float num = -2.76076847742355e-16f;
    num = fmaf(num, x2, 2.00018790482477e-13f);
    num = fmaf(num, x2, -8.60467152213735e-11f);
    num = fmaf(num, x2, 5.12229709037114e-08f);
    num = fmaf(num, x2, 1.48572235717979e-05f);
    num = fmaf(num, x2, 6.37261928875436e-04f);
    num = fmaf(num, x2, 4.89352455891786e-03f);
    num = num * xc;
    float den = 1.19825839466702e-06f;
    den = fmaf(den, x2, 1.18534705686654e-04f);
    den = fmaf(den, x2, 2.26843463243900e-03f);
    den = fmaf(den, x2, 4.89352518554385e-03f);
    float r = num / den;
    return (fabsf(x) < 0.0004f) ? x : r;
}
__device__ __forceinline__ float xla_logistic(float x) {
    return 0.5f + 0.5f * xla_tanh(0.5f * x);
}

// argmax combine: higher value wins; tie -> lower linear index
__device__ __forceinline__ void amax(float& v, int& i, float ov, int oi) {
    if (ov > v || (ov == v && oi < i)) { v = ov; i = oi; }
}

// ---- kInit: zero per-run accumulators (graph-replay safe) ----
__global__ void kInit() {
    int t = threadIdx.x;
    for (int i = t; i < NB; i += 1024) g_hist[i] = 0;
    if (t == 0) { g_selCount = 0; g_fallback = 0; }
}

// ---- kA: score map + histogram + per-tile argmax (tile max kept for fallback) ----
__global__ void kA(const float* __restrict__ in) {
    __shared__ float wV[8];
    __shared__ int   wI[8];
    int t = threadIdx.x;                 // 0..255
    int lane = t & 31, warp = t >> 5;
    int row = t >> 3;
    int c4  = (t & 7) << 2;
    int x0 = (blockIdx.x << 5) + c4;
    int y  = (blockIdx.y << 5) + row;
    int idx = (y << 10) + x0;
    float4 v = *reinterpret_cast<const float4*>(in + idx);
    float vv[4] = {v.x, v.y, v.z, v.w};
    float sc[4];
    float mv = NEG_INF; int mi = 0x7FFFFFFF;
    #pragma unroll
    for (int j = 0; j < 4; j++) {
        float conf = xla_logistic(vv[j]);
        bool cand = (conf > 0.8f);
        float s = cand ? conf : NEG_INF;
        sc[j] = s;
        if (cand) {
            unsigned bits = __float_as_uint(conf);
            unsigned bin = (bits - B0BITS) >> 10;
            if (bin > NB - 1) bin = NB - 1;
            atomicAdd(&g_hist[bin], 1);
        }
        amax(mv, mi, s, idx + j);
    }
    *reinterpret_cast<float4*>(g_scores + idx) = make_float4(sc[0], sc[1], sc[2], sc[3]);

    #pragma unroll
    for (int off = 16; off; off >>= 1) {
        float ov = __shfl_down_sync(0xFFFFFFFFu, mv, off);
        int   oi = __shfl_down_sync(0xFFFFFFFFu, mi, off);
        amax(mv, mi, ov, oi);
    }
    if (lane == 0) { wV[warp] = mv; wI[warp] = mi; }
    __syncthreads();
    if (t == 0) {
        #pragma unroll
        for (int w = 1; w < 8; w++) amax(wV[0], wI[0], wV[w], wI[w]);
        int tt = blockIdx.y * NTILE + blockIdx.x;
        g_tileMax[tt] = wV[0];
        g_tileIdx[tt] = wI[0];
    }
}

// ---- kB0: find score-bit threshold from histogram (top >= KTGT candidates) ----
__global__ void __launch_bounds__(1024, 1) kB0() {
    __shared__ int sm[1024];
    int t = threadIdx.x;
    int base = t * 4;
    int c = 0;
    #pragma unroll
    for (int b = 0; b < 4; b++) { int bi = base + b; c += (bi < NB) ? g_hist[bi] : 0; }
    sm[t] = c;
    __syncthreads();
    for (int off = 1; off < 1024; off <<= 1) {
        int v = (t + off < 1024) ? sm[t + off] : 0;
        __syncthreads();
        sm[t] += v;
        __syncthreads();
    }
    int St  = sm[t];
    int St1 = (t < 1023) ? sm[t + 1] : 0;
    if (t == 0) g_totalCand = St;
    bool here = (St >= KTGT) && (St1 < KTGT);
    if (here) {
        int run = St1;
        int T = base;
        for (int b = 3; b >= 0; b--) {
            int bi = base + b;
            int h = (bi < NB) ? g_hist[bi] : 0;
            run += h;
            if (run >= KTGT) { T = bi; break; }
        }
        g_thrBits = B0BITS + ((unsigned)T << 10);
    }
    if (t == 0 && St < KTGT) g_thrBits = B0BITS;   // fewer than KTGT total: take all
}

// ---- kB1: compact candidates >= threshold into g_sel as sortable keys ----
__global__ void kB1() {
    int gid = blockIdx.x * blockDim.x + threadIdx.x;   // 0..262143
    float thr = __uint_as_float(g_thrBits);
    int idx0 = gid << 2;
    float4 v = *reinterpret_cast<const float4*>(g_scores + idx0);
    float vv[4] = {v.x, v.y, v.z, v.w};
    #pragma unroll
    for (int j = 0; j < 4; j++) {
        float s = vv[j];
        if (s >= thr) {                               // -inf excluded; positive-float order == bit order
            int pos = atomicAdd(&g_selCount, 1);
            if (pos < CAP) {
                unsigned long long key =
                    ((unsigned long long)(~__float_as_uint(s)) << 32) | (unsigned)(idx0 + j);
                g_sel[pos] = key;                      // ascending sort => score desc, idx asc
            }
        }
    }
}

// ---- kB2: bitonic sort (2048) + single-warp greedy NMS scan ----
__global__ void __launch_bounds__(1024, 1) kB2() {
    __shared__ unsigned long long s[CAP];
    __shared__ int2 kept[MAXR];
    int tid = threadIdx.x;
    int n = g_selCount; if (n > CAP) n = CAP;
    for (int i = tid; i < CAP; i += 1024) s[i] = (i < n) ? g_sel[i] : 0xFFFFFFFFFFFFFFFFull;
    __syncthreads();
    for (int k = 2; k <= CAP; k <<= 1) {
        for (int j = k >> 1; j > 0; j >>= 1) {
            for (int i = tid; i < CAP; i += 1024) {
                int ixj = i ^ j;
                if (ixj > i) {
                    unsigned long long a = s[i], b = s[ixj];
                    bool up = ((i & k) == 0);
                    if ((a > b) == up) { s[i] = b; s[ixj] = a; }
                }
            }
            __syncthreads();
        }
    }
    if (tid < 32) {
        int lane = tid;
        int nk = 0;
        for (int i = 0; i < n && nk < MAXR; i++) {
            unsigned long long key = s[i];
            unsigned idx = (unsigned)key;
            int cx = idx & (S - 1), cy = idx >> 10;
            bool rej = false;
            for (int k2 = lane; k2 < nk; k2 += 32) {
                int dx = kept[k2].x - cx, dy = kept[k2].y - cy;
                rej |= (dx * dx + dy * dy <= 100);
            }
            rej = __any_sync(0xFFFFFFFFu, rej);
            if (!rej) {
                if (lane == 0) {
                    kept[nk] = make_int2(cx, cy);
                    g_rootX[nk] = cx; g_rootY[nk] = cy; g_valid[nk] = 1;
                }
                nk++;
                __syncwarp();
            }
        }
        for (int r = nk + lane; r < MAXR; r += 32) { g_rootX[r] = 0; g_rootY[r] = 0; g_valid[r] = 0; }
        if (lane == 0) {
            int sc = g_selCount;
            g_fallback = ((sc > CAP) || (nk < MAXR && g_totalCand > n)) ? 1 : 0;
        }
    }
}

// ---- kFB: gated fallback — full greedy NMS (round-2 proven path) ----
__global__ void __launch_bounds__(1024, 1) kFB() {
    if (g_fallback == 0) return;
    __shared__ float sVal[NTILES];
    __shared__ int   sIdx[NTILES];
    __shared__ float wV[32];
    __shared__ int   wI[32];
    __shared__ float tV[32];
    __shared__ int   tI[32];
    __shared__ int   sBestI;

    int tid  = threadIdx.x;
    int lane = tid & 31;
    int warp = tid >> 5;

    sVal[tid] = g_tileMax[tid];
    sIdx[tid] = g_tileIdx[tid];
    __syncthreads();

    for (int r = 0; r < MAXR; r++) {
        float mv = sVal[tid]; int mi = sIdx[tid];
        #pragma unroll
        for (int off = 16; off; off >>= 1) {
            float ov = __shfl_down_sync(0xFFFFFFFFu, mv, off);
            int   oi = __shfl_down_sync(0xFFFFFFFFu, mi, off);
            amax(mv, mi, ov, oi);
        }
        if (lane == 0) { wV[warp] = mv; wI[warp] = mi; }
        __syncthreads();
        if (warp == 0) {
            mv = wV[lane]; mi = wI[lane];
            #pragma unroll
            for (int off = 16; off; off >>= 1) {
                float ov = __shfl_down_sync(0xFFFFFFFFu, mv, off);
                int   oi = __shfl_down_sync(0xFFFFFFFFu, mi, off);
                amax(mv, mi, ov, oi);
            }
            if (lane == 0) {
                sBestI = mi;
                g_rootX[r] = mi & (S - 1);
                g_rootY[r] = mi >> 10;
                g_valid[r] = (mv > NEG_INF) ? 1 : 0;
            }
        }
        __syncthreads();

        int bI = sBestI;
        int cx = bI & (S - 1);
        int cy = bI >> 10;

        int tx0 = max(cx - 10, 0) >> 5, tx1 = min(cx + 10, S - 1) >> 5;
        int ty0 = max(cy - 10, 0) >> 5, ty1 = min(cy + 10, S - 1) >> 5;
        int ntx = tx1 - tx0 + 1;
        int nty = ty1 - ty0 + 1;
        int nt  = ntx * nty;

        int ti = tid >> 8;
        int p  = tid & 255;

        float mv2 = NEG_INF; int mi2 = 0x7FFFFFFF;
        if (ti < nt) {
            int ttx = tx0 + (ti % ntx);
            int tty = ty0 + (ti / ntx);
            int tbx = ttx << 5, tby = tty << 5;
            #pragma unroll
            for (int q = 0; q < 4; q++) {
                int pp = p + q * 256;
                int py = tby + (pp >> 5);
                int px = tbx + (pp & 31);
                int pix = (py << 10) + px;
                float sv = g_scores[pix];
                int dx = px - cx, dy = py - cy;
                if (dx * dx + dy * dy <= 100) {
                    g_scores[pix] = NEG_INF;
                    sv = NEG_INF;
                }
                amax(mv2, mi2, sv, pix);
            }
        }
        #pragma unroll
        for (int off = 16; off; off >>= 1) {
            float ov = __shfl_down_sync(0xFFFFFFFFu, mv2, off);
            int   oi = __shfl_down_sync(0xFFFFFFFFu, mi2, off);
            amax(mv2, mi2, ov, oi);
        }
        if (lane == 0) { tV[warp] = mv2; tI[warp] = mi2; }
        __syncthreads();
        if (tid < nt) {
            float bv = NEG_INF; int bi = 0x7FFFFFFF;
            #pragma unroll
            for (int w = 0; w < 8; w++) amax(bv, bi, tV[tid * 8 + w], tI[tid * 8 + w]);
            int ttx = tx0 + (tid % ntx);
            int tty = ty0 + (tid / ntx);
            int tt  = tty * NTILE + ttx;
            sVal[tt] = bv;
            sIdx[tt] = bi;
        }
        __syncthreads();
    }
}

// ---- kC: displacement gather + outputs ----
// out layout (float32, 9472): root[256][2] | kp[256][17][2] | valid[256]
__global__ void kC(const float* __restrict__ in, float* __restrict__ out) {
    int r = blockIdx.x;
    int k = threadIdx.x;
    int cx = g_rootX[r];
    int cy = g_rootY[r];
    float m = g_valid[r] ? 1.0f : 0.0f;
    float z = sqrtf(2.0f) * 1024.0f;

    if (k < NKP) {
        int base = (1 + 2 * k) * SS + (cy << 10) + cx;
        float dx = xla_tanh(in[base]);
        float dy = xla_tanh(in[base + SS]);
        float kx = dx * z + (float)cx;
        float ky = dy * z + (float)cy;
        float ddx = kx - (float)cx;
        float ddy = ky - (float)cy;
        float d = sqrtf(ddx * ddx + ddy * ddy);
        if (d < 2.0f) { kx = 0.0f; ky = 0.0f; }
        out[512 + r * 34 + 2 * k]     = kx * m * 4.0f;
        out[512 + r * 34 + 2 * k + 1] = ky * m * 4.0f;
    }
    if (k == NKP) {
        out[r * 2]     = (float)cx * m * 4.0f;
        out[r * 2 + 1] = (float)cy * m * 4.0f;
        out[512 + 256 * 34 + r] = m;
    }
}

extern "C" void kernel_launch(void* const* d_in, const int* in_sizes, int n_in,
                              void* d_out, int out_size) {
    const float* x = (const float*)d_in[0];
    float* out = (float*)d_out;

    kInit<<<1, 1024>>>();
    kA<<<dim3(32, 32), 256>>>(x);
    kB0<<<1, 1024>>>();
    kB1<<<256, 1024>>>();
    kB2<<<1, 1024>>>();
    kFB<<<1, 1024>>>();
    kC<<<MAXR, 32>>>(x, out);
}